// round 8
// baseline (speedup 1.0000x reference)
#include <cuda_runtime.h>
#include <cuda_fp16.h>
#include <cstdint>

// ---------------------------------------------------------------------------
// SimpleRNN: logits = W_out( scan_tanh( W_ih·emb[x] + b_ih , W_hh, b_hh ) ) + b_out
// B=8, S=2048, E=256, H=512, V=16000
// Round 7:
//  - rnn_scan reworked: mbarrier parity signaling instead of barrier.cluster,
//    in-warp shuffle reduction (out=tid>>3, kc=tid&7), bank-conflict-free
//    rotated LDS, xp prefetch before wait.
//  - logits_mma: single __syncthreads per mainloop iter, prefetch-before-compute.
// ---------------------------------------------------------------------------

#define B_  8
#define S_  2048
#define E_  256
#define H_  512
#define V_  16000
#define MTOT (B_ * S_)                      // 16384
static const long long VOUT = (long long)B_ * S_ * V_;   // 262,144,000

// Scratch (device globals: no allocation allowed)
__device__ float  g_xproj[(size_t)MTOT * H_];    // 33.5 MB
__device__ __half g_h16  [(size_t)MTOT * H_];    // 16.8 MB
__device__ __half g_w16  [(size_t)V_  * H_];     // 16.4 MB
__device__ float  g_dummy_hf[B_ * H_];

// ---------------- small PTX helpers -----------------------------------------
__device__ __forceinline__ void ffma2(unsigned long long& acc,
                                      unsigned long long a,
                                      unsigned long long b) {
    asm("fma.rn.f32x2 %0, %1, %2, %0;" : "+l"(acc) : "l"(a), "l"(b));
}
__device__ __forceinline__ unsigned long long pack2(float x, float y) {
    unsigned long long r;
    asm("mov.b64 %0, {%1, %2};" : "=l"(r) : "f"(x), "f"(y));
    return r;
}
__device__ __forceinline__ void unpack2(unsigned long long v, float& lo, float& hi) {
    asm("mov.b64 {%0, %1}, %2;" : "=f"(lo), "=f"(hi) : "l"(v));
}
__device__ __forceinline__ uint32_t smem_u32(const void* p) {
    uint32_t a;
    asm("{ .reg .u64 t; cvta.to.shared.u64 t, %1; cvt.u32.u64 %0, t; }"
        : "=r"(a) : "l"(p));
    return a;
}
__device__ __forceinline__ void cp_async16(uint32_t saddr, const void* gaddr) {
    asm volatile("cp.async.cg.shared.global [%0], [%1], 16;"
                 :: "r"(saddr), "l"(gaddr));
}
#define CP_COMMIT() asm volatile("cp.async.commit_group;" ::: "memory")
template <int N>
__device__ __forceinline__ void cp_wait() {
    asm volatile("cp.async.wait_group %0;" :: "n"(N) : "memory");
}
__device__ __forceinline__ void ldsm4(uint32_t addr, uint32_t& r0, uint32_t& r1,
                                      uint32_t& r2, uint32_t& r3) {
    asm volatile("ldmatrix.sync.aligned.m8n8.x4.shared.b16 {%0,%1,%2,%3}, [%4];"
                 : "=r"(r0), "=r"(r1), "=r"(r2), "=r"(r3) : "r"(addr));
}
__device__ __forceinline__ void mma_f16(float* d,
                                        uint32_t a0, uint32_t a1,
                                        uint32_t a2, uint32_t a3,
                                        uint32_t b0, uint32_t b1) {
    asm volatile("mma.sync.aligned.m16n8k16.row.col.f32.f16.f16.f32 "
                 "{%0,%1,%2,%3}, {%4,%5,%6,%7}, {%8,%9}, {%0,%1,%2,%3};"
                 : "+f"(d[0]), "+f"(d[1]), "+f"(d[2]), "+f"(d[3])
                 : "r"(a0), "r"(a1), "r"(a2), "r"(a3), "r"(b0), "r"(b1));
}
// mbarrier: wait with cluster-scope acquire (DSMEM data visibility)
__device__ __forceinline__ void mbar_wait_cl(uint32_t addr, uint32_t parity) {
    uint32_t done = 0;
    while (!done) {
        asm volatile(
            "{\n\t.reg .pred p;\n\t"
            "mbarrier.try_wait.parity.acquire.cluster.shared::cta.b64 p, [%1], %2, 0x989680;\n\t"
            "selp.b32 %0, 1, 0, p;\n\t}"
            : "=r"(done) : "r"(addr), "r"(parity) : "memory");
    }
}

// ---------------------------------------------------------------------------
// Kernel 0: W_out fp32 -> fp16
// ---------------------------------------------------------------------------
__global__ void to_half(const float* __restrict__ src,
                        __half* __restrict__ dst, int n)
{
    int i = blockIdx.x * blockDim.x + threadIdx.x;
    int stride = gridDim.x * blockDim.x;
    for (; i < n; i += stride) dst[i] = __float2half(src[i]);
}

// ---------------------------------------------------------------------------
// Kernel 1: x_proj SGEMM (unchanged, ~123us)
// ---------------------------------------------------------------------------
template <bool GATHER>
__global__ __launch_bounds__(256, 2)
void gemm_nt(const float* __restrict__ A, const float* __restrict__ Bmat,
             const float* __restrict__ bias, float* __restrict__ C,
             const int* __restrict__ idx, int M, int N, int K)
{
    __shared__ float As[2][8][128];
    __shared__ float Bs[2][8][128];

    const int tid  = threadIdx.x;
    const int mblk = blockIdx.y * 128;
    const int nblk = blockIdx.x * 128;

    const int arow = tid >> 1;
    const int kq   = (tid & 1) * 4;

    const float* Aptr;
    if (GATHER) Aptr = A + (size_t)idx[mblk + arow] * K;
    else        Aptr = A + (size_t)(mblk + arow) * K;
    const float* Bptr = Bmat + (size_t)(nblk + arow) * K;

    const int ty = tid >> 4;
    const int tx = tid & 15;

    unsigned long long acc2[8][4];
    #pragma unroll
    for (int i = 0; i < 8; i++)
        #pragma unroll
        for (int p = 0; p < 4; p++) acc2[i][p] = 0ull;

    {
        float4 a4 = *(const float4*)(Aptr + kq);
        float4 b4 = *(const float4*)(Bptr + kq);
        #pragma unroll
        for (int i = 0; i < 4; i++) {
            As[0][kq + i][arow] = ((const float*)&a4)[i];
            Bs[0][kq + i][arow] = ((const float*)&b4)[i];
        }
    }
    __syncthreads();

    const int nkt = K >> 3;
    for (int kt = 0; kt < nkt; kt++) {
        const int cur = kt & 1, nxt = cur ^ 1;
        float4 a4n, b4n;
        const bool more = (kt + 1 < nkt);
        if (more) {
            a4n = *(const float4*)(Aptr + (kt + 1) * 8 + kq);
            b4n = *(const float4*)(Bptr + (kt + 1) * 8 + kq);
        }
        #pragma unroll
        for (int k = 0; k < 8; k++) {
            float af[8];
            *(float4*)&af[0] = *(const float4*)&As[cur][k][ty * 8];
            *(float4*)&af[4] = *(const float4*)&As[cur][k][ty * 8 + 4];
            unsigned long long bp[4];
            const unsigned long long* bq =
                (const unsigned long long*)&Bs[cur][k][tx * 8];
            #pragma unroll
            for (int p = 0; p < 4; p++) bp[p] = bq[p];
            #pragma unroll
            for (int i = 0; i < 8; i++) {
                unsigned long long ad = pack2(af[i], af[i]);
                #pragma unroll
                for (int p = 0; p < 4; p++) ffma2(acc2[i][p], ad, bp[p]);
            }
        }
        if (more) {
            #pragma unroll
            for (int i = 0; i < 4; i++) {
                As[nxt][kq + i][arow] = ((const float*)&a4n)[i];
                Bs[nxt][kq + i][arow] = ((const float*)&b4n)[i];
            }
        }
        __syncthreads();
    }

    float bv[8];
    #pragma unroll
    for (int j = 0; j < 8; j++) bv[j] = bias[nblk + tx * 8 + j];

    #pragma unroll
    for (int i = 0; i < 8; i++) {
        size_t row = (size_t)(mblk + ty * 8 + i);
        float* cp = C + row * (size_t)N + nblk + tx * 8;
        float v[8];
        #pragma unroll
        for (int p = 0; p < 4; p++) {
            float lo, hi;
            unpack2(acc2[i][p], lo, hi);
            v[2 * p]     = lo + bv[2 * p];
            v[2 * p + 1] = hi + bv[2 * p + 1];
        }
        *(float4*)cp       = make_float4(v[0], v[1], v[2], v[3]);
        *(float4*)(cp + 4) = make_float4(v[4], v[5], v[6], v[7]);
    }
}

// ---------------------------------------------------------------------------
// Kernel 2: RNN scan — mbarrier-signaled cluster pipeline.
// 8 clusters (1/batch) x 8 CTAs x 512 threads. CTA rank owns 64 h-dims.
// Thread: out = tid>>3 (0..63), kc = tid&7 (k-chunk of 64).
// Per step: wait mbar (acquire.cluster) -> 32 packed FMAs (rotated,
// conflict-free) -> 3x shfl reduce -> lanes kc==0: tanh, hseq fp16 store,
// 8 remote h stores (mapa + st.shared::cluster) -> fence -> bar.sync ->
// tid<8: one release-arrive to each CTA's barrier for the next buffer.
// ---------------------------------------------------------------------------
__global__ __launch_bounds__(512, 1) __cluster_dims__(8, 1, 1)
void rnn_scan(const float* __restrict__ xproj,
              const float* __restrict__ hidden0,
              const float* __restrict__ W_hh,
              const float* __restrict__ b_hh,
              __half* __restrict__ hs16,
              float* __restrict__ hfinal)
{
    __shared__ float h_buf[2][H_];
    __shared__ unsigned long long mbar[2];

    const int tid   = threadIdx.x;
    const int batch = blockIdx.x >> 3;
    const int rank  = blockIdx.x & 7;
    const int out   = tid >> 3;          // 0..63
    const int kc    = tid & 7;           // 0..7
    const int grow  = rank * 64 + out;
    const int rot   = 2 * kc;            // u64 rotation for bank spread
    const bool prod = (kc == 0);

    // W_hh slice, rotated to match the rotated h reads
    unsigned long long w2[32];
    {
        const unsigned long long* wq =
            (const unsigned long long*)(W_hh + (size_t)grow * H_ + kc * 64);
        #pragma unroll
        for (int j = 0; j < 32; j++) w2[j] = wq[(j + rot) & 31];
    }

    h_buf[0][tid] = hidden0[batch * H_ + tid];
    const float bhh = prod ? b_hh[grow] : 0.f;

    const uint32_t mb0 = smem_u32(&mbar[0]);
    const uint32_t mb1 = smem_u32(&mbar[1]);
    if (tid < 2) {
        asm volatile("mbarrier.init.shared.b64 [%0], %1;"
                     :: "r"(tid == 0 ? mb0 : mb1), "r"(8u) : "memory");
    }
    __syncthreads();
    // all CTAs: barriers initialized + h0 loaded before any remote traffic
    asm volatile("barrier.cluster.arrive.aligned;" ::: "memory");
    asm volatile("barrier.cluster.wait.aligned;"   ::: "memory");

    const float* xp_b = xproj + (size_t)batch * S_ * H_ + grow;
    __half*      hh_b = hs16  + (size_t)batch * S_ * H_ + grow;

    int ph0 = 0, ph1 = 0;
    float hn = 0.f;

    for (int t = 0; t < S_; t++) {
        const int pb = t & 1;

        // prefetch x_proj (independent of the barrier)
        float xp = 0.f;
        if (prod) xp = __ldg(xp_b + (size_t)t * H_);

        if (t > 0) {
            if (pb) { mbar_wait_cl(mb1, (uint32_t)ph1); ph1 ^= 1; }
            else    { mbar_wait_cl(mb0, (uint32_t)ph0); ph0 ^= 1; }
        }

        // partial dot over 64 k-values: 2 chains of 16 packed FMAs
        const unsigned long long* h64 =
            (const unsigned long long*)&h_buf[pb][kc * 64];
        unsigned long long a0 = 0ull, a1 = 0ull;
        #pragma unroll
        for (int j = 0; j < 16; j++) {
            ffma2(a0, w2[2 * j],     h64[(2 * j     + rot) & 31]);
            ffma2(a1, w2[2 * j + 1], h64[(2 * j + 1 + rot) & 31]);
        }
        float l0, hi0, l1, hi1;
        unpack2(a0, l0, hi0);
        unpack2(a1, l1, hi1);
        float s = (l0 + hi0) + (l1 + hi1);
        // reduce over the 8 lanes sharing this output
        s += __shfl_xor_sync(0xffffffffu, s, 4, 8);
        s += __shfl_xor_sync(0xffffffffu, s, 2, 8);
        s += __shfl_xor_sync(0xffffffffu, s, 1, 8);

        const bool last = (t == S_ - 1);
        if (prod) {
            hn = tanhf(s + xp + bhh);
            hh_b[(size_t)t * H_] = __float2half(hn);
            if (!last) {
                uint32_t laddr = smem_u32(&h_buf[pb ^ 1][grow]);
                #pragma unroll
                for (int pr = 0; pr < 8; pr++) {
                    uint32_t paddr;
                    asm("mapa.shared::cluster.u32 %0, %1, %2;"
                        : "=r"(paddr) : "r"(laddr), "r"(pr));
                    asm volatile("st.shared::cluster.f32 [%0], %1;"
                                 :: "r"(paddr), "f"(hn) : "memory");
                }
                asm volatile("fence.acq_rel.cluster;" ::: "memory");
            }
        }
        if (!last) {
            __syncthreads();     // all reads of h_buf[pb] + all stores done
            if (tid < 8) {
                const uint32_t lm = pb ? mb0 : mb1;   // barrier of next buffer
                asm volatile(
                    "{\n\t.reg .b32 ra;\n\t"
                    "mapa.shared::cluster.u32 ra, %0, %1;\n\t"
                    "mbarrier.arrive.release.cluster.shared::cluster.b64 _, [ra];\n\t}"
                    :: "r"(lm), "r"(tid) : "memory");
            }
        }
    }

    // drain any in-flight DSMEM traffic before CTAs exit
    asm volatile("barrier.cluster.arrive.aligned;" ::: "memory");
    asm volatile("barrier.cluster.wait.aligned;"   ::: "memory");

    if (prod) hfinal[batch * H_ + grow] = hn;
}

// ---------------------------------------------------------------------------
// Kernel 3: logits GEMM via mma.sync fp16, single term D = A*B.
// 128x128 CTA tile, 8 warps (4M x 2N), K-chunk 64, 3-stage cp.async pipeline
// with ONE __syncthreads per iter (prefetch-before-compute), 2 CTAs/SM.
// ---------------------------------------------------------------------------
#define OP_PITCH  144                       // bytes per smem row (64 fp16 + pad)
#define OP_SZ     (128 * OP_PITCH)          // 18432 B per operand tile
#define STAGE_SZ  (2 * OP_SZ)               // A, B
#define NSTAGE    3
#define LOGITS_SMEM (NSTAGE * STAGE_SZ)     // 110592 B

__global__ __launch_bounds__(256, 2)
void logits_mma(const __half* __restrict__ Ah,
                const __half* __restrict__ Bw,
                const float* __restrict__ bias,
                float* __restrict__ C)
{
    extern __shared__ char dsm[];
    const uint32_t sbase = smem_u32(dsm);

    const int tid  = threadIdx.x;
    const int warp = tid >> 5, lane = tid & 31;
    const int wm = warp & 3;                 // 0..3  (M)
    const int wn = warp >> 2;                // 0..1  (N)
    const int mblk = blockIdx.y * 128;
    const int nblk = blockIdx.x * 128;

    const char* opg[2] = { (const char*)Ah, (const char*)Bw };
    const int   r0op[2] = { mblk, nblk };

    auto load_stage = [&](int kc, int st) {
        const uint32_t sst = sbase + (uint32_t)st * STAGE_SZ;
        #pragma unroll
        for (int op = 0; op < 2; op++) {
            #pragma unroll
            for (int j = 0; j < 4; j++) {
                int u = tid + 256 * j;
                int row = u >> 3, cc = u & 7;
                const void* g = opg[op] +
                    (size_t)(r0op[op] + row) * (H_ * 2) + kc * 128 + cc * 16;
                uint32_t s = sst + (uint32_t)op * OP_SZ + row * OP_PITCH + cc * 16;
                cp_async16(s, g);
            }
        }
        CP_COMMIT();
    };

    float acc[2][8][4];
    #pragma unroll
    for (int mi = 0; mi < 2; mi++)
        #pragma unroll
        for (int ni = 0; ni < 8; ni++)
            #pragma unroll
            for (int q = 0; q < 4; q++) acc[mi][ni][q] = 0.f;

    load_stage(0, 0);
    load_stage(1, 1);

    const int arow  = wm * 32 + (lane & 15);          // + mi*16
    const int aoff  = (lane >> 4) * 16;
    const int nrow  = wn * 64 + (lane & 7) + ((lane >> 4) & 1) * 8;  // + g*16
    const int boff  = ((lane >> 3) & 1) * 16;

    #pragma unroll 1
    for (int kc = 0; kc < 8; kc++) {
        const int st = kc - (kc / NSTAGE) * NSTAGE;   // kc % 3
        cp_wait<1>();
        __syncthreads();    // all warps past iter kc-1 -> stage (kc+2)%3 free

        if (kc + 2 < 8) load_stage(kc + 2, (kc + 2) % NSTAGE);
        else            CP_COMMIT();   // empty group keeps accounting aligned

        const uint32_t sst = sbase + (uint32_t)st * STAGE_SZ;
        const uint32_t ahb = sst;
        const uint32_t bwb = sst + OP_SZ;

        #pragma unroll
        for (int ks = 0; ks < 4; ks++) {
            const int kb = ks * 32;   // bytes (16 fp16)
            uint32_t ah[2][4];
            #pragma unroll
            for (int mi = 0; mi < 2; mi++)
                ldsm4(ahb + (arow + mi * 16) * OP_PITCH + kb + aoff,
                      ah[mi][0], ah[mi][1], ah[mi][2], ah[mi][3]);
            #pragma unroll
            for (int g = 0; g < 4; g++) {
                uint32_t bh[4];
                ldsm4(bwb + (nrow + g * 16) * OP_PITCH + kb + boff,
                      bh[0], bh[1], bh[2], bh[3]);
                #pragma unroll
                for (int mi = 0; mi < 2; mi++) {
                    mma_f16(acc[mi][2 * g],
                            ah[mi][0], ah[mi][1], ah[mi][2], ah[mi][3],
                            bh[0], bh[1]);
                    mma_f16(acc[mi][2 * g + 1],
                            ah[mi][0], ah[mi][1], ah[mi][2], ah[mi][3],
                            bh[2], bh[3]);
                }
            }
        }
    }

    // epilogue
    const int rg = mblk + wm * 32 + (lane >> 2);
    const int cg = nblk + wn * 64 + (lane & 3) * 2;
    #pragma unroll
    for (int mi = 0; mi < 2; mi++) {
        #pragma unroll
        for (int ni = 0; ni < 8; ni++) {
            const int row = rg + mi * 16;
            const int col = cg + ni * 8;
            const float b0 = __ldg(bias + col);
            const float b1 = __ldg(bias + col + 1);
            float2 v0 = make_float2(acc[mi][ni][0] + b0, acc[mi][ni][1] + b1);
            float2 v1 = make_float2(acc[mi][ni][2] + b0, acc[mi][ni][3] + b1);
            *(float2*)(C + (size_t)row * V_ + col)       = v0;
            *(float2*)(C + (size_t)(row + 8) * V_ + col) = v1;
        }
    }
}

// ---------------------------------------------------------------------------
// Launch
// inputs: 0=x(i32)[B,S] 1=hidden[B,H] 2=embedding[V,E] 3=W_ih[H,E]
//         4=W_hh[H,H] 5=b_ih[H] 6=b_hh[H] 7=W_out[V,H] 8=b_out[V]
// output: logits [B,S,V] then h_final [B,H]
// ---------------------------------------------------------------------------
extern "C" void kernel_launch(void* const* d_in, const int* in_sizes, int n_in,
                              void* d_out, int out_size)
{
    const int*   x         = (const int*)  d_in[0];
    const float* hidden    = (const float*)d_in[1];
    const float* embedding = (const float*)d_in[2];
    const float* W_ih      = (const float*)d_in[3];
    const float* W_hh      = (const float*)d_in[4];
    const float* b_ih      = (const float*)d_in[5];
    const float* b_hh      = (const float*)d_in[6];
    const float* W_out     = (const float*)d_in[7];
    const float* b_out     = (const float*)d_in[8];
    float* out = (float*)d_out;

    float *xproj, *dummy;
    __half *h16, *w16;
    cudaGetSymbolAddress((void**)&xproj, g_xproj);
    cudaGetSymbolAddress((void**)&h16,   g_h16);
    cudaGetSymbolAddress((void**)&w16,   g_w16);
    cudaGetSymbolAddress((void**)&dummy, g_dummy_hf);

    float* hfin = ((long long)out_size >= VOUT + (long long)B_ * H_)
                      ? (out + VOUT) : dummy;

    static bool attr_done = false;
    if (!attr_done) {
        cudaFuncSetAttribute(logits_mma,
                             cudaFuncAttributeMaxDynamicSharedMemorySize,
                             LOGITS_SMEM);
        attr_done = true;
    }

    // 0) W_out -> fp16
    to_half<<<2048, 256>>>(W_out, w16, V_ * H_);

    // 1) x_proj = emb[x] @ W_ih^T + b_ih     [16384,512]
    gemm_nt<true><<<dim3(H_ / 128, MTOT / 128), 256>>>(
        embedding, W_ih, b_ih, xproj, x, MTOT, H_, E_);

    // 2) sequential scan -> hseq (fp16), h_final
    rnn_scan<<<64, 512>>>(xproj, hidden, W_hh, b_hh, h16, hfin);

    // 3) logits = hseq @ W_out^T + b_out    [16384,16000] via mma.sync
    logits_mma<<<dim3(V_ / 128, MTOT / 128), 256, LOGITS_SMEM>>>(
        h16, w16, b_out, out);
}

// round 9
// speedup vs baseline: 1.1703x; 1.1703x over previous
#include <cuda_runtime.h>
#include <cuda_fp16.h>
#include <cstdint>

// ---------------------------------------------------------------------------
// SimpleRNN: logits = W_out( scan_tanh( W_ih·emb[x] + b_ih , W_hh, b_hh ) ) + b_out
// B=8, S=2048, E=256, H=512, V=16000
// Round 8: scan sync reverted to barrier.cluster (R7 mbarrier scheme regressed);
// kept: shfl-based in-warp reduction (one syncthreads/step), xp prefetch,
// R7 single-sync logits pipeline.
// ---------------------------------------------------------------------------

#define B_  8
#define S_  2048
#define E_  256
#define H_  512
#define V_  16000
#define MTOT (B_ * S_)                      // 16384
static const long long VOUT = (long long)B_ * S_ * V_;   // 262,144,000

// Scratch (device globals: no allocation allowed)
__device__ float  g_xproj[(size_t)MTOT * H_];    // 33.5 MB
__device__ __half g_h16  [(size_t)MTOT * H_];    // 16.8 MB
__device__ __half g_w16  [(size_t)V_  * H_];     // 16.4 MB
__device__ float  g_dummy_hf[B_ * H_];

// ---------------- small PTX helpers -----------------------------------------
__device__ __forceinline__ void ffma2(unsigned long long& acc,
                                      unsigned long long a,
                                      unsigned long long b) {
    asm("fma.rn.f32x2 %0, %1, %2, %0;" : "+l"(acc) : "l"(a), "l"(b));
}
__device__ __forceinline__ unsigned long long pack2(float x, float y) {
    unsigned long long r;
    asm("mov.b64 %0, {%1, %2};" : "=l"(r) : "f"(x), "f"(y));
    return r;
}
__device__ __forceinline__ void unpack2(unsigned long long v, float& lo, float& hi) {
    asm("mov.b64 {%0, %1}, %2;" : "=f"(lo), "=f"(hi) : "l"(v));
}
__device__ __forceinline__ uint32_t smem_u32(const void* p) {
    uint32_t a;
    asm("{ .reg .u64 t; cvta.to.shared.u64 t, %1; cvt.u32.u64 %0, t; }"
        : "=r"(a) : "l"(p));
    return a;
}
__device__ __forceinline__ void cp_async16(uint32_t saddr, const void* gaddr) {
    asm volatile("cp.async.cg.shared.global [%0], [%1], 16;"
                 :: "r"(saddr), "l"(gaddr));
}
#define CP_COMMIT() asm volatile("cp.async.commit_group;" ::: "memory")
template <int N>
__device__ __forceinline__ void cp_wait() {
    asm volatile("cp.async.wait_group %0;" :: "n"(N) : "memory");
}
__device__ __forceinline__ void ldsm4(uint32_t addr, uint32_t& r0, uint32_t& r1,
                                      uint32_t& r2, uint32_t& r3) {
    asm volatile("ldmatrix.sync.aligned.m8n8.x4.shared.b16 {%0,%1,%2,%3}, [%4];"
                 : "=r"(r0), "=r"(r1), "=r"(r2), "=r"(r3) : "r"(addr));
}
__device__ __forceinline__ void mma_f16(float* d,
                                        uint32_t a0, uint32_t a1,
                                        uint32_t a2, uint32_t a3,
                                        uint32_t b0, uint32_t b1) {
    asm volatile("mma.sync.aligned.m16n8k16.row.col.f32.f16.f16.f32 "
                 "{%0,%1,%2,%3}, {%4,%5,%6,%7}, {%8,%9}, {%0,%1,%2,%3};"
                 : "+f"(d[0]), "+f"(d[1]), "+f"(d[2]), "+f"(d[3])
                 : "r"(a0), "r"(a1), "r"(a2), "r"(a3), "r"(b0), "r"(b1));
}

// ---------------------------------------------------------------------------
// Kernel 0: W_out fp32 -> fp16
// ---------------------------------------------------------------------------
__global__ void to_half(const float* __restrict__ src,
                        __half* __restrict__ dst, int n)
{
    int i = blockIdx.x * blockDim.x + threadIdx.x;
    int stride = gridDim.x * blockDim.x;
    for (; i < n; i += stride) dst[i] = __float2half(src[i]);
}

// ---------------------------------------------------------------------------
// Kernel 1: x_proj SGEMM (unchanged, ~123us)
// ---------------------------------------------------------------------------
template <bool GATHER>
__global__ __launch_bounds__(256, 2)
void gemm_nt(const float* __restrict__ A, const float* __restrict__ Bmat,
             const float* __restrict__ bias, float* __restrict__ C,
             const int* __restrict__ idx, int M, int N, int K)
{
    __shared__ float As[2][8][128];
    __shared__ float Bs[2][8][128];

    const int tid  = threadIdx.x;
    const int mblk = blockIdx.y * 128;
    const int nblk = blockIdx.x * 128;

    const int arow = tid >> 1;
    const int kq   = (tid & 1) * 4;

    const float* Aptr;
    if (GATHER) Aptr = A + (size_t)idx[mblk + arow] * K;
    else        Aptr = A + (size_t)(mblk + arow) * K;
    const float* Bptr = Bmat + (size_t)(nblk + arow) * K;

    const int ty = tid >> 4;
    const int tx = tid & 15;

    unsigned long long acc2[8][4];
    #pragma unroll
    for (int i = 0; i < 8; i++)
        #pragma unroll
        for (int p = 0; p < 4; p++) acc2[i][p] = 0ull;

    {
        float4 a4 = *(const float4*)(Aptr + kq);
        float4 b4 = *(const float4*)(Bptr + kq);
        #pragma unroll
        for (int i = 0; i < 4; i++) {
            As[0][kq + i][arow] = ((const float*)&a4)[i];
            Bs[0][kq + i][arow] = ((const float*)&b4)[i];
        }
    }
    __syncthreads();

    const int nkt = K >> 3;
    for (int kt = 0; kt < nkt; kt++) {
        const int cur = kt & 1, nxt = cur ^ 1;
        float4 a4n, b4n;
        const bool more = (kt + 1 < nkt);
        if (more) {
            a4n = *(const float4*)(Aptr + (kt + 1) * 8 + kq);
            b4n = *(const float4*)(Bptr + (kt + 1) * 8 + kq);
        }
        #pragma unroll
        for (int k = 0; k < 8; k++) {
            float af[8];
            *(float4*)&af[0] = *(const float4*)&As[cur][k][ty * 8];
            *(float4*)&af[4] = *(const float4*)&As[cur][k][ty * 8 + 4];
            unsigned long long bp[4];
            const unsigned long long* bq =
                (const unsigned long long*)&Bs[cur][k][tx * 8];
            #pragma unroll
            for (int p = 0; p < 4; p++) bp[p] = bq[p];
            #pragma unroll
            for (int i = 0; i < 8; i++) {
                unsigned long long ad = pack2(af[i], af[i]);
                #pragma unroll
                for (int p = 0; p < 4; p++) ffma2(acc2[i][p], ad, bp[p]);
            }
        }
        if (more) {
            #pragma unroll
            for (int i = 0; i < 4; i++) {
                As[nxt][kq + i][arow] = ((const float*)&a4n)[i];
                Bs[nxt][kq + i][arow] = ((const float*)&b4n)[i];
            }
        }
        __syncthreads();
    }

    float bv[8];
    #pragma unroll
    for (int j = 0; j < 8; j++) bv[j] = bias[nblk + tx * 8 + j];

    #pragma unroll
    for (int i = 0; i < 8; i++) {
        size_t row = (size_t)(mblk + ty * 8 + i);
        float* cp = C + row * (size_t)N + nblk + tx * 8;
        float v[8];
        #pragma unroll
        for (int p = 0; p < 4; p++) {
            float lo, hi;
            unpack2(acc2[i][p], lo, hi);
            v[2 * p]     = lo + bv[2 * p];
            v[2 * p + 1] = hi + bv[2 * p + 1];
        }
        *(float4*)cp       = make_float4(v[0], v[1], v[2], v[3]);
        *(float4*)(cp + 4) = make_float4(v[4], v[5], v[6], v[7]);
    }
}

// ---------------------------------------------------------------------------
// Kernel 2: RNN scan — barrier.cluster per step (R6 sync, known-good) with
// shfl reduction (R7 mapping, one __syncthreads per step).
// 8 clusters (1/batch) x 8 CTAs x 512 threads. CTA rank owns 64 h-dims.
// Thread: out = tid>>3 (0..63), kc = tid&7 (k-chunk of 64).
// Per step: FMAs(read h_buf[pb]) -> 3x shfl -> prod lanes: tanh, 8 remote
// stores to h_buf[pb^1], gmem fp16 store -> __syncthreads ->
// barrier.cluster arrive+wait (release/acquire orders the DSMEM stores).
// ---------------------------------------------------------------------------
__global__ __launch_bounds__(512, 1) __cluster_dims__(8, 1, 1)
void rnn_scan(const float* __restrict__ xproj,
              const float* __restrict__ hidden0,
              const float* __restrict__ W_hh,
              const float* __restrict__ b_hh,
              __half* __restrict__ hs16,
              float* __restrict__ hfinal)
{
    __shared__ float h_buf[2][H_];

    const int tid   = threadIdx.x;
    const int batch = blockIdx.x >> 3;
    const int rank  = blockIdx.x & 7;
    const int out   = tid >> 3;          // 0..63
    const int kc    = tid & 7;           // 0..7
    const int grow  = rank * 64 + out;
    const int rot   = 2 * kc;            // u64 rotation for bank spread
    const bool prod = (kc == 0);

    // W_hh slice, rotated to match the rotated h reads
    unsigned long long w2[32];
    {
        const unsigned long long* wq =
            (const unsigned long long*)(W_hh + (size_t)grow * H_ + kc * 64);
        #pragma unroll
        for (int j = 0; j < 32; j++) w2[j] = wq[(j + rot) & 31];
    }

    h_buf[0][tid] = hidden0[batch * H_ + tid];
    const float bhh = prod ? b_hh[grow] : 0.f;
    __syncthreads();
    asm volatile("barrier.cluster.arrive.aligned;" ::: "memory");
    asm volatile("barrier.cluster.wait.aligned;"   ::: "memory");

    const float* xp_b = xproj + (size_t)batch * S_ * H_ + grow;
    __half*      hh_b = hs16  + (size_t)batch * S_ * H_ + grow;

    float hn = 0.f;
    for (int t = 0; t < S_; t++) {
        const int pb = t & 1;

        // prefetch x_proj (independent of smem state)
        float xp = 0.f;
        if (prod) xp = __ldg(xp_b + (size_t)t * H_);

        // partial dot over 64 k-values: 2 chains of 16 packed FMAs
        const unsigned long long* h64 =
            (const unsigned long long*)&h_buf[pb][kc * 64];
        unsigned long long a0 = 0ull, a1 = 0ull;
        #pragma unroll
        for (int j = 0; j < 16; j++) {
            ffma2(a0, w2[2 * j],     h64[(2 * j     + rot) & 31]);
            ffma2(a1, w2[2 * j + 1], h64[(2 * j + 1 + rot) & 31]);
        }
        float l0, hi0, l1, hi1;
        unpack2(a0, l0, hi0);
        unpack2(a1, l1, hi1);
        float s = (l0 + hi0) + (l1 + hi1);
        // reduce over the 8 lanes sharing this output
        s += __shfl_xor_sync(0xffffffffu, s, 4, 8);
        s += __shfl_xor_sync(0xffffffffu, s, 2, 8);
        s += __shfl_xor_sync(0xffffffffu, s, 1, 8);

        if (prod) {
            hn = tanhf(s + xp + bhh);
            // broadcast into every cluster CTA's other h buffer (incl. self)
            uint32_t laddr = smem_u32(&h_buf[pb ^ 1][grow]);
            #pragma unroll
            for (int pr = 0; pr < 8; pr++) {
                uint32_t paddr;
                asm("mapa.shared::cluster.u32 %0, %1, %2;"
                    : "=r"(paddr) : "r"(laddr), "r"(pr));
                asm volatile("st.shared::cluster.f32 [%0], %1;"
                             :: "r"(paddr), "f"(hn) : "memory");
            }
            hh_b[(size_t)t * H_] = __float2half(hn);
        }
        __syncthreads();   // all reads of h_buf[pb] done, stores issued
        // arrive releases our DSMEM stores; wait acquires peers' stores
        asm volatile("barrier.cluster.arrive.aligned;" ::: "memory");
        asm volatile("barrier.cluster.wait.aligned;"   ::: "memory");
    }

    if (prod) hfinal[batch * H_ + grow] = hn;
}

// ---------------------------------------------------------------------------
// Kernel 3: logits GEMM via mma.sync fp16, single term D = A*B.
// 128x128 CTA tile, 8 warps (4M x 2N), K-chunk 64, 3-stage cp.async pipeline
// with ONE __syncthreads per iter (prefetch-before-compute), 2 CTAs/SM.
// (Measured 814us in R8 profile — kept verbatim.)
// ---------------------------------------------------------------------------
#define OP_PITCH  144                       // bytes per smem row (64 fp16 + pad)
#define OP_SZ     (128 * OP_PITCH)          // 18432 B per operand tile
#define STAGE_SZ  (2 * OP_SZ)               // A, B
#define NSTAGE    3
#define LOGITS_SMEM (NSTAGE * STAGE_SZ)     // 110592 B

__global__ __launch_bounds__(256, 2)
void logits_mma(const __half* __restrict__ Ah,
                const __half* __restrict__ Bw,
                const float* __restrict__ bias,
                float* __restrict__ C)
{
    extern __shared__ char dsm[];
    const uint32_t sbase = smem_u32(dsm);

    const int tid  = threadIdx.x;
    const int warp = tid >> 5, lane = tid & 31;
    const int wm = warp & 3;                 // 0..3  (M)
    const int wn = warp >> 2;                // 0..1  (N)
    const int mblk = blockIdx.y * 128;
    const int nblk = blockIdx.x * 128;

    const char* opg[2] = { (const char*)Ah, (const char*)Bw };
    const int   r0op[2] = { mblk, nblk };

    auto load_stage = [&](int kc, int st) {
        const uint32_t sst = sbase + (uint32_t)st * STAGE_SZ;
        #pragma unroll
        for (int op = 0; op < 2; op++) {
            #pragma unroll
            for (int j = 0; j < 4; j++) {
                int u = tid + 256 * j;
                int row = u >> 3, cc = u & 7;
                const void* g = opg[op] +
                    (size_t)(r0op[op] + row) * (H_ * 2) + kc * 128 + cc * 16;
                uint32_t s = sst + (uint32_t)op * OP_SZ + row * OP_PITCH + cc * 16;
                cp_async16(s, g);
            }
        }
        CP_COMMIT();
    };

    float acc[2][8][4];
    #pragma unroll
    for (int mi = 0; mi < 2; mi++)
        #pragma unroll
        for (int ni = 0; ni < 8; ni++)
            #pragma unroll
            for (int q = 0; q < 4; q++) acc[mi][ni][q] = 0.f;

    load_stage(0, 0);
    load_stage(1, 1);

    const int arow  = wm * 32 + (lane & 15);          // + mi*16
    const int aoff  = (lane >> 4) * 16;
    const int nrow  = wn * 64 + (lane & 7) + ((lane >> 4) & 1) * 8;  // + g*16
    const int boff  = ((lane >> 3) & 1) * 16;

    #pragma unroll 1
    for (int kc = 0; kc < 8; kc++) {
        const int st = kc - (kc / NSTAGE) * NSTAGE;   // kc % 3
        cp_wait<1>();
        __syncthreads();    // all warps past iter kc-1 -> stage (kc+2)%3 free

        if (kc + 2 < 8) load_stage(kc + 2, (kc + 2) % NSTAGE);
        else            CP_COMMIT();   // empty group keeps accounting aligned

        const uint32_t sst = sbase + (uint32_t)st * STAGE_SZ;
        const uint32_t ahb = sst;
        const uint32_t bwb = sst + OP_SZ;

        #pragma unroll
        for (int ks = 0; ks < 4; ks++) {
            const int kb = ks * 32;   // bytes (16 fp16)
            uint32_t ah[2][4];
            #pragma unroll
            for (int mi = 0; mi < 2; mi++)
                ldsm4(ahb + (arow + mi * 16) * OP_PITCH + kb + aoff,
                      ah[mi][0], ah[mi][1], ah[mi][2], ah[mi][3]);
            #pragma unroll
            for (int g = 0; g < 4; g++) {
                uint32_t bh[4];
                ldsm4(bwb + (nrow + g * 16) * OP_PITCH + kb + boff,
                      bh[0], bh[1], bh[2], bh[3]);
                #pragma unroll
                for (int mi = 0; mi < 2; mi++) {
                    mma_f16(acc[mi][2 * g],
                            ah[mi][0], ah[mi][1], ah[mi][2], ah[mi][3],
                            bh[0], bh[1]);
                    mma_f16(acc[mi][2 * g + 1],
                            ah[mi][0], ah[mi][1], ah[mi][2], ah[mi][3],
                            bh[2], bh[3]);
                }
            }
        }
    }

    // epilogue
    const int rg = mblk + wm * 32 + (lane >> 2);
    const int cg = nblk + wn * 64 + (lane & 3) * 2;
    #pragma unroll
    for (int mi = 0; mi < 2; mi++) {
        #pragma unroll
        for (int ni = 0; ni < 8; ni++) {
            const int row = rg + mi * 16;
            const int col = cg + ni * 8;
            const float b0 = __ldg(bias + col);
            const float b1 = __ldg(bias + col + 1);
            float2 v0 = make_float2(acc[mi][ni][0] + b0, acc[mi][ni][1] + b1);
            float2 v1 = make_float2(acc[mi][ni][2] + b0, acc[mi][ni][3] + b1);
            *(float2*)(C + (size_t)row * V_ + col)       = v0;
            *(float2*)(C + (size_t)(row + 8) * V_ + col) = v1;
        }
    }
}

// ---------------------------------------------------------------------------
// Launch
// inputs: 0=x(i32)[B,S] 1=hidden[B,H] 2=embedding[V,E] 3=W_ih[H,E]
//         4=W_hh[H,H] 5=b_ih[H] 6=b_hh[H] 7=W_out[V,H] 8=b_out[V]
// output: logits [B,S,V] then h_final [B,H]
// ---------------------------------------------------------------------------
extern "C" void kernel_launch(void* const* d_in, const int* in_sizes, int n_in,
                              void* d_out, int out_size)
{
    const int*   x         = (const int*)  d_in[0];
    const float* hidden    = (const float*)d_in[1];
    const float* embedding = (const float*)d_in[2];
    const float* W_ih      = (const float*)d_in[3];
    const float* W_hh      = (const float*)d_in[4];
    const float* b_ih      = (const float*)d_in[5];
    const float* b_hh      = (const float*)d_in[6];
    const float* W_out     = (const float*)d_in[7];
    const float* b_out     = (const float*)d_in[8];
    float* out = (float*)d_out;

    float *xproj, *dummy;
    __half *h16, *w16;
    cudaGetSymbolAddress((void**)&xproj, g_xproj);
    cudaGetSymbolAddress((void**)&h16,   g_h16);
    cudaGetSymbolAddress((void**)&w16,   g_w16);
    cudaGetSymbolAddress((void**)&dummy, g_dummy_hf);

    float* hfin = ((long long)out_size >= VOUT + (long long)B_ * H_)
                      ? (out + VOUT) : dummy;

    static bool attr_done = false;
    if (!attr_done) {
        cudaFuncSetAttribute(logits_mma,
                             cudaFuncAttributeMaxDynamicSharedMemorySize,
                             LOGITS_SMEM);
        attr_done = true;
    }

    // 0) W_out -> fp16
    to_half<<<2048, 256>>>(W_out, w16, V_ * H_);

    // 1) x_proj = emb[x] @ W_ih^T + b_ih     [16384,512]
    gemm_nt<true><<<dim3(H_ / 128, MTOT / 128), 256>>>(
        embedding, W_ih, b_ih, xproj, x, MTOT, H_, E_);

    // 2) sequential scan -> hseq (fp16), h_final
    rnn_scan<<<64, 512>>>(xproj, hidden, W_hh, b_hh, h16, hfin);

    // 3) logits = hseq @ W_out^T + b_out    [16384,16000] via mma.sync
    logits_mma<<<dim3(V_ / 128, MTOT / 128), 256, LOGITS_SMEM>>>(
        h16, w16, b_out, out);
}

// round 10
// speedup vs baseline: 1.3396x; 1.1446x over previous
#include <cuda_runtime.h>
#include <cuda_fp16.h>
#include <cstdint>

// ---------------------------------------------------------------------------
// SimpleRNN: logits = W_out( scan_tanh( W_ih·emb[x] + b_ih , W_hh, b_hh ) ) + b_out
// B=8, S=2048, E=256, H=512, V=16000
// Round 9: scan = R6 FMA phase (uniform broadcast LDS, immediate offsets)
// + distributed tail (all threads redundantly reduce+tanh, ONE remote store
// per thread). Logits kernel = R7 version (measured 815us), unchanged.
// ---------------------------------------------------------------------------

#define B_  8
#define S_  2048
#define E_  256
#define H_  512
#define V_  16000
#define MTOT (B_ * S_)                      // 16384
static const long long VOUT = (long long)B_ * S_ * V_;   // 262,144,000

// Scratch (device globals: no allocation allowed)
__device__ float  g_xproj[(size_t)MTOT * H_];    // 33.5 MB
__device__ __half g_h16  [(size_t)MTOT * H_];    // 16.8 MB
__device__ __half g_w16  [(size_t)V_  * H_];     // 16.4 MB
__device__ float  g_dummy_hf[B_ * H_];

// ---------------- small PTX helpers -----------------------------------------
__device__ __forceinline__ void ffma2(unsigned long long& acc,
                                      unsigned long long a,
                                      unsigned long long b) {
    asm("fma.rn.f32x2 %0, %1, %2, %0;" : "+l"(acc) : "l"(a), "l"(b));
}
__device__ __forceinline__ unsigned long long pack2(float x, float y) {
    unsigned long long r;
    asm("mov.b64 %0, {%1, %2};" : "=l"(r) : "f"(x), "f"(y));
    return r;
}
__device__ __forceinline__ void unpack2(unsigned long long v, float& lo, float& hi) {
    asm("mov.b64 {%0, %1}, %2;" : "=f"(lo), "=f"(hi) : "l"(v));
}
__device__ __forceinline__ uint32_t smem_u32(const void* p) {
    uint32_t a;
    asm("{ .reg .u64 t; cvta.to.shared.u64 t, %1; cvt.u32.u64 %0, t; }"
        : "=r"(a) : "l"(p));
    return a;
}
__device__ __forceinline__ void cp_async16(uint32_t saddr, const void* gaddr) {
    asm volatile("cp.async.cg.shared.global [%0], [%1], 16;"
                 :: "r"(saddr), "l"(gaddr));
}
#define CP_COMMIT() asm volatile("cp.async.commit_group;" ::: "memory")
template <int N>
__device__ __forceinline__ void cp_wait() {
    asm volatile("cp.async.wait_group %0;" :: "n"(N) : "memory");
}
__device__ __forceinline__ void ldsm4(uint32_t addr, uint32_t& r0, uint32_t& r1,
                                      uint32_t& r2, uint32_t& r3) {
    asm volatile("ldmatrix.sync.aligned.m8n8.x4.shared.b16 {%0,%1,%2,%3}, [%4];"
                 : "=r"(r0), "=r"(r1), "=r"(r2), "=r"(r3) : "r"(addr));
}
__device__ __forceinline__ void mma_f16(float* d,
                                        uint32_t a0, uint32_t a1,
                                        uint32_t a2, uint32_t a3,
                                        uint32_t b0, uint32_t b1) {
    asm volatile("mma.sync.aligned.m16n8k16.row.col.f32.f16.f16.f32 "
                 "{%0,%1,%2,%3}, {%4,%5,%6,%7}, {%8,%9}, {%0,%1,%2,%3};"
                 : "+f"(d[0]), "+f"(d[1]), "+f"(d[2]), "+f"(d[3])
                 : "r"(a0), "r"(a1), "r"(a2), "r"(a3), "r"(b0), "r"(b1));
}

// ---------------------------------------------------------------------------
// Kernel 0: W_out fp32 -> fp16
// ---------------------------------------------------------------------------
__global__ void to_half(const float* __restrict__ src,
                        __half* __restrict__ dst, int n)
{
    int i = blockIdx.x * blockDim.x + threadIdx.x;
    int stride = gridDim.x * blockDim.x;
    for (; i < n; i += stride) dst[i] = __float2half(src[i]);
}

// ---------------------------------------------------------------------------
// Kernel 1: x_proj SGEMM (unchanged, ~123us)
// ---------------------------------------------------------------------------
template <bool GATHER>
__global__ __launch_bounds__(256, 2)
void gemm_nt(const float* __restrict__ A, const float* __restrict__ Bmat,
             const float* __restrict__ bias, float* __restrict__ C,
             const int* __restrict__ idx, int M, int N, int K)
{
    __shared__ float As[2][8][128];
    __shared__ float Bs[2][8][128];

    const int tid  = threadIdx.x;
    const int mblk = blockIdx.y * 128;
    const int nblk = blockIdx.x * 128;

    const int arow = tid >> 1;
    const int kq   = (tid & 1) * 4;

    const float* Aptr;
    if (GATHER) Aptr = A + (size_t)idx[mblk + arow] * K;
    else        Aptr = A + (size_t)(mblk + arow) * K;
    const float* Bptr = Bmat + (size_t)(nblk + arow) * K;

    const int ty = tid >> 4;
    const int tx = tid & 15;

    unsigned long long acc2[8][4];
    #pragma unroll
    for (int i = 0; i < 8; i++)
        #pragma unroll
        for (int p = 0; p < 4; p++) acc2[i][p] = 0ull;

    {
        float4 a4 = *(const float4*)(Aptr + kq);
        float4 b4 = *(const float4*)(Bptr + kq);
        #pragma unroll
        for (int i = 0; i < 4; i++) {
            As[0][kq + i][arow] = ((const float*)&a4)[i];
            Bs[0][kq + i][arow] = ((const float*)&b4)[i];
        }
    }
    __syncthreads();

    const int nkt = K >> 3;
    for (int kt = 0; kt < nkt; kt++) {
        const int cur = kt & 1, nxt = cur ^ 1;
        float4 a4n, b4n;
        const bool more = (kt + 1 < nkt);
        if (more) {
            a4n = *(const float4*)(Aptr + (kt + 1) * 8 + kq);
            b4n = *(const float4*)(Bptr + (kt + 1) * 8 + kq);
        }
        #pragma unroll
        for (int k = 0; k < 8; k++) {
            float af[8];
            *(float4*)&af[0] = *(const float4*)&As[cur][k][ty * 8];
            *(float4*)&af[4] = *(const float4*)&As[cur][k][ty * 8 + 4];
            unsigned long long bp[4];
            const unsigned long long* bq =
                (const unsigned long long*)&Bs[cur][k][tx * 8];
            #pragma unroll
            for (int p = 0; p < 4; p++) bp[p] = bq[p];
            #pragma unroll
            for (int i = 0; i < 8; i++) {
                unsigned long long ad = pack2(af[i], af[i]);
                #pragma unroll
                for (int p = 0; p < 4; p++) ffma2(acc2[i][p], ad, bp[p]);
            }
        }
        if (more) {
            #pragma unroll
            for (int i = 0; i < 4; i++) {
                As[nxt][kq + i][arow] = ((const float*)&a4n)[i];
                Bs[nxt][kq + i][arow] = ((const float*)&b4n)[i];
            }
        }
        __syncthreads();
    }

    float bv[8];
    #pragma unroll
    for (int j = 0; j < 8; j++) bv[j] = bias[nblk + tx * 8 + j];

    #pragma unroll
    for (int i = 0; i < 8; i++) {
        size_t row = (size_t)(mblk + ty * 8 + i);
        float* cp = C + row * (size_t)N + nblk + tx * 8;
        float v[8];
        #pragma unroll
        for (int p = 0; p < 4; p++) {
            float lo, hi;
            unpack2(acc2[i][p], lo, hi);
            v[2 * p]     = lo + bv[2 * p];
            v[2 * p + 1] = hi + bv[2 * p + 1];
        }
        *(float4*)cp       = make_float4(v[0], v[1], v[2], v[3]);
        *(float4*)(cp + 4) = make_float4(v[4], v[5], v[6], v[7]);
    }
}

// ---------------------------------------------------------------------------
// Kernel 2: RNN scan. 8 clusters (1/batch) x 8 CTAs x 512 threads.
// R6 mapping: kc = tid>>6 (k-chunk), out = tid&63 (output dim).
// Phase 1 (R6-identical): warp-uniform broadcast LDS of h_buf[pb][kc*64..],
// immediate offsets, 2 packed-FMA chains -> part[kc][out] STS.
// Phase 2 (new): after ONE __syncthreads, ALL threads reduce part[0..7][out]
// (conflict-free: bank = out%32) + redundant tanh (deterministic, identical
// across kc-groups), then each thread does ONE st.shared::cluster of its
// output value to rank kc. Store precedes own barrier.cluster.arrive
// (release), wait acquires peers' stores — same ordering as proven R6.
// ---------------------------------------------------------------------------
__global__ __launch_bounds__(512, 1) __cluster_dims__(8, 1, 1)
void rnn_scan(const float* __restrict__ xproj,
              const float* __restrict__ hidden0,
              const float* __restrict__ W_hh,
              const float* __restrict__ b_hh,
              __half* __restrict__ hs16,
              float* __restrict__ hfinal)
{
    __shared__ float h_buf[2][H_];
    __shared__ float part[8][64];

    const int tid   = threadIdx.x;
    const int batch = blockIdx.x >> 3;
    const int rank  = blockIdx.x & 7;
    const int kc    = tid >> 6;          // 0..7 : k-chunk AND store-target rank
    const int out   = tid & 63;          // 0..63
    const int grow  = rank * 64 + out;

    // W_hh slice (row grow, k-chunk kc) -> 32 packed pairs
    unsigned long long w2[32];
    {
        const unsigned long long* wq =
            (const unsigned long long*)(W_hh + (size_t)grow * H_ + kc * 64);
        #pragma unroll
        for (int j = 0; j < 32; j++) w2[j] = wq[j];
    }

    h_buf[0][tid] = hidden0[batch * H_ + tid];
    const float bhh = b_hh[grow];
    __syncthreads();
    asm volatile("barrier.cluster.arrive.aligned;" ::: "memory");
    asm volatile("barrier.cluster.wait.aligned;"   ::: "memory");

    const float* xp_b = xproj + (size_t)batch * S_ * H_ + grow;
    __half*      hh_b = hs16  + (size_t)batch * S_ * H_ + grow;

    // precompute remote address bases for this thread's single store target
    uint32_t raddr0, raddr1;
    {
        uint32_t l0 = smem_u32(&h_buf[0][grow]);
        uint32_t l1 = smem_u32(&h_buf[1][grow]);
        asm("mapa.shared::cluster.u32 %0, %1, %2;"
            : "=r"(raddr0) : "r"(l0), "r"(kc));
        asm("mapa.shared::cluster.u32 %0, %1, %2;"
            : "=r"(raddr1) : "r"(l1), "r"(kc));
    }

    float hn = 0.f;
    for (int t = 0; t < S_; t++) {
        const int pb = t & 1;

        // prefetch x_proj for this thread's output (8-way gmem broadcast)
        const float xp = __ldg(xp_b + (size_t)t * H_);

        // phase 1: partial dot over 64 k (warp-uniform broadcast LDS,
        // immediate offsets, two chains)
        const unsigned long long* h64 =
            (const unsigned long long*)&h_buf[pb][kc * 64];
        unsigned long long a0 = 0ull, a1 = 0ull;
        #pragma unroll
        for (int j = 0; j < 16; j++) {
            ffma2(a0, w2[2 * j],     h64[2 * j]);
            ffma2(a1, w2[2 * j + 1], h64[2 * j + 1]);
        }
        float l0, hi0, l1, hi1;
        unpack2(a0, l0, hi0);
        unpack2(a1, l1, hi1);
        part[kc][out] = (l0 + hi0) + (l1 + hi1);
        __syncthreads();

        // phase 2: all threads reduce + tanh (redundant across kc-groups,
        // deterministic); one remote store each.
        float s = xp + bhh;
        #pragma unroll
        for (int c = 0; c < 8; c++) s += part[c][out];
        hn = tanhf(s);

        if (kc == 0) hh_b[(size_t)t * H_] = __float2half(hn);

        asm volatile("st.shared::cluster.f32 [%0], %1;"
                     :: "r"(pb ? raddr0 : raddr1), "f"(hn) : "memory");

        // arrive releases our store; wait acquires peers' stores
        asm volatile("barrier.cluster.arrive.aligned;" ::: "memory");
        asm volatile("barrier.cluster.wait.aligned;"   ::: "memory");
    }

    if (kc == 0) hfinal[batch * H_ + grow] = hn;
}

// ---------------------------------------------------------------------------
// Kernel 3: logits GEMM via mma.sync fp16, single term D = A*B.
// 128x128 CTA tile, 8 warps (4M x 2N), K-chunk 64, 3-stage cp.async pipeline
// with ONE __syncthreads per iter (prefetch-before-compute), 2 CTAs/SM.
// (Measured 815us — unchanged.)
// ---------------------------------------------------------------------------
#define OP_PITCH  144                       // bytes per smem row (64 fp16 + pad)
#define OP_SZ     (128 * OP_PITCH)          // 18432 B per operand tile
#define STAGE_SZ  (2 * OP_SZ)               // A, B
#define NSTAGE    3
#define LOGITS_SMEM (NSTAGE * STAGE_SZ)     // 110592 B

__global__ __launch_bounds__(256, 2)
void logits_mma(const __half* __restrict__ Ah,
                const __half* __restrict__ Bw,
                const float* __restrict__ bias,
                float* __restrict__ C)
{
    extern __shared__ char dsm[];
    const uint32_t sbase = smem_u32(dsm);

    const int tid  = threadIdx.x;
    const int warp = tid >> 5, lane = tid & 31;
    const int wm = warp & 3;                 // 0..3  (M)
    const int wn = warp >> 2;                // 0..1  (N)
    const int mblk = blockIdx.y * 128;
    const int nblk = blockIdx.x * 128;

    const char* opg[2] = { (const char*)Ah, (const char*)Bw };
    const int   r0op[2] = { mblk, nblk };

    auto load_stage = [&](int kc, int st) {
        const uint32_t sst = sbase + (uint32_t)st * STAGE_SZ;
        #pragma unroll
        for (int op = 0; op < 2; op++) {
            #pragma unroll
            for (int j = 0; j < 4; j++) {
                int u = tid + 256 * j;
                int row = u >> 3, cc = u & 7;
                const void* g = opg[op] +
                    (size_t)(r0op[op] + row) * (H_ * 2) + kc * 128 + cc * 16;
                uint32_t s = sst + (uint32_t)op * OP_SZ + row * OP_PITCH + cc * 16;
                cp_async16(s, g);
            }
        }
        CP_COMMIT();
    };

    float acc[2][8][4];
    #pragma unroll
    for (int mi = 0; mi < 2; mi++)
        #pragma unroll
        for (int ni = 0; ni < 8; ni++)
            #pragma unroll
            for (int q = 0; q < 4; q++) acc[mi][ni][q] = 0.f;

    load_stage(0, 0);
    load_stage(1, 1);

    const int arow  = wm * 32 + (lane & 15);          // + mi*16
    const int aoff  = (lane >> 4) * 16;
    const int nrow  = wn * 64 + (lane & 7) + ((lane >> 4) & 1) * 8;  // + g*16
    const int boff  = ((lane >> 3) & 1) * 16;

    #pragma unroll 1
    for (int kc = 0; kc < 8; kc++) {
        const int st = kc - (kc / NSTAGE) * NSTAGE;   // kc % 3
        cp_wait<1>();
        __syncthreads();    // all warps past iter kc-1 -> stage (kc+2)%3 free

        if (kc + 2 < 8) load_stage(kc + 2, (kc + 2) % NSTAGE);
        else            CP_COMMIT();   // empty group keeps accounting aligned

        const uint32_t sst = sbase + (uint32_t)st * STAGE_SZ;
        const uint32_t ahb = sst;
        const uint32_t bwb = sst + OP_SZ;

        #pragma unroll
        for (int ks = 0; ks < 4; ks++) {
            const int kb = ks * 32;   // bytes (16 fp16)
            uint32_t ah[2][4];
            #pragma unroll
            for (int mi = 0; mi < 2; mi++)
                ldsm4(ahb + (arow + mi * 16) * OP_PITCH + kb + aoff,
                      ah[mi][0], ah[mi][1], ah[mi][2], ah[mi][3]);
            #pragma unroll
            for (int g = 0; g < 4; g++) {
                uint32_t bh[4];
                ldsm4(bwb + (nrow + g * 16) * OP_PITCH + kb + boff,
                      bh[0], bh[1], bh[2], bh[3]);
                #pragma unroll
                for (int mi = 0; mi < 2; mi++) {
                    mma_f16(acc[mi][2 * g],
                            ah[mi][0], ah[mi][1], ah[mi][2], ah[mi][3],
                            bh[0], bh[1]);
                    mma_f16(acc[mi][2 * g + 1],
                            ah[mi][0], ah[mi][1], ah[mi][2], ah[mi][3],
                            bh[2], bh[3]);
                }
            }
        }
    }

    // epilogue
    const int rg = mblk + wm * 32 + (lane >> 2);
    const int cg = nblk + wn * 64 + (lane & 3) * 2;
    #pragma unroll
    for (int mi = 0; mi < 2; mi++) {
        #pragma unroll
        for (int ni = 0; ni < 8; ni++) {
            const int row = rg + mi * 16;
            const int col = cg + ni * 8;
            const float b0 = __ldg(bias + col);
            const float b1 = __ldg(bias + col + 1);
            float2 v0 = make_float2(acc[mi][ni][0] + b0, acc[mi][ni][1] + b1);
            float2 v1 = make_float2(acc[mi][ni][2] + b0, acc[mi][ni][3] + b1);
            *(float2*)(C + (size_t)row * V_ + col)       = v0;
            *(float2*)(C + (size_t)(row + 8) * V_ + col) = v1;
        }
    }
}

// ---------------------------------------------------------------------------
// Launch
// inputs: 0=x(i32)[B,S] 1=hidden[B,H] 2=embedding[V,E] 3=W_ih[H,E]
//         4=W_hh[H,H] 5=b_ih[H] 6=b_hh[H] 7=W_out[V,H] 8=b_out[V]
// output: logits [B,S,V] then h_final [B,H]
// ---------------------------------------------------------------------------
extern "C" void kernel_launch(void* const* d_in, const int* in_sizes, int n_in,
                              void* d_out, int out_size)
{
    const int*   x         = (const int*)  d_in[0];
    const float* hidden    = (const float*)d_in[1];
    const float* embedding = (const float*)d_in[2];
    const float* W_ih      = (const float*)d_in[3];
    const float* W_hh      = (const float*)d_in[4];
    const float* b_ih      = (const float*)d_in[5];
    const float* b_hh      = (const float*)d_in[6];
    const float* W_out     = (const float*)d_in[7];
    const float* b_out     = (const float*)d_in[8];
    float* out = (float*)d_out;

    float *xproj, *dummy;
    __half *h16, *w16;
    cudaGetSymbolAddress((void**)&xproj, g_xproj);
    cudaGetSymbolAddress((void**)&h16,   g_h16);
    cudaGetSymbolAddress((void**)&w16,   g_w16);
    cudaGetSymbolAddress((void**)&dummy, g_dummy_hf);

    float* hfin = ((long long)out_size >= VOUT + (long long)B_ * H_)
                      ? (out + VOUT) : dummy;

    static bool attr_done = false;
    if (!attr_done) {
        cudaFuncSetAttribute(logits_mma,
                             cudaFuncAttributeMaxDynamicSharedMemorySize,
                             LOGITS_SMEM);
        attr_done = true;
    }

    // 0) W_out -> fp16
    to_half<<<2048, 256>>>(W_out, w16, V_ * H_);

    // 1) x_proj = emb[x] @ W_ih^T + b_ih     [16384,512]
    gemm_nt<true><<<dim3(H_ / 128, MTOT / 128), 256>>>(
        embedding, W_ih, b_ih, xproj, x, MTOT, H_, E_);

    // 2) sequential scan -> hseq (fp16), h_final
    rnn_scan<<<64, 512>>>(xproj, hidden, W_hh, b_hh, h16, hfin);

    // 3) logits = hseq @ W_out^T + b_out    [16384,16000] via mma.sync
    logits_mma<<<dim3(V_ / 128, MTOT / 128), 256, LOGITS_SMEM>>>(
        h16, w16, b_out, out);
}

// round 12
// speedup vs baseline: 1.5998x; 1.1943x over previous
#include <cuda_runtime.h>
#include <cuda_fp16.h>
#include <cstdint>

// ---------------------------------------------------------------------------
// SimpleRNN: logits = W_out( scan_tanh( W_ih·emb[x] + b_ih , W_hh, b_hh ) ) + b_out
// B=8, S=2048, E=256, H=512, V=16000
// Round 11: R10 fused design with the hseq store index fixed
// (hh_b[t*H_ + tid], was hh_b[t*H_] — the sole cause of the R10 failure).
// 64 scan CTAs (8 clusters of 8, exact R6-measured body) + 72 worker CTAs
// running the logits GEMM as a ticket-ordered persistent tile loop,
// overlapped via gpu-scope progress counters; scan CTAs join the drain.
// ---------------------------------------------------------------------------

#define B_  8
#define S_  2048
#define E_  256
#define H_  512
#define V_  16000
#define MTOT (B_ * S_)                      // 16384
static const long long VOUT = (long long)B_ * S_ * V_;   // 262,144,000

// Scratch (device globals: no allocation allowed)
__device__ float  g_xproj[(size_t)MTOT * H_];    // 33.5 MB
__device__ __half g_h16  [(size_t)MTOT * H_];    // 16.8 MB
__device__ __half g_w16  [(size_t)V_  * H_];     // 16.4 MB
__device__ float  g_dummy_hf[B_ * H_];
__device__ unsigned int g_progress[B_][8];       // per (batch, 256-step chunk)
__device__ unsigned int g_ticket;

// ---------------- small PTX helpers -----------------------------------------
__device__ __forceinline__ void ffma2(unsigned long long& acc,
                                      unsigned long long a,
                                      unsigned long long b) {
    asm("fma.rn.f32x2 %0, %1, %2, %0;" : "+l"(acc) : "l"(a), "l"(b));
}
__device__ __forceinline__ unsigned long long pack2(float x, float y) {
    unsigned long long r;
    asm("mov.b64 %0, {%1, %2};" : "=l"(r) : "f"(x), "f"(y));
    return r;
}
__device__ __forceinline__ void unpack2(unsigned long long v, float& lo, float& hi) {
    asm("mov.b64 {%0, %1}, %2;" : "=f"(lo), "=f"(hi) : "l"(v));
}
__device__ __forceinline__ uint32_t smem_u32(const void* p) {
    uint32_t a;
    asm("{ .reg .u64 t; cvta.to.shared.u64 t, %1; cvt.u32.u64 %0, t; }"
        : "=r"(a) : "l"(p));
    return a;
}
__device__ __forceinline__ void cp_async16(uint32_t saddr, const void* gaddr) {
    asm volatile("cp.async.cg.shared.global [%0], [%1], 16;"
                 :: "r"(saddr), "l"(gaddr));
}
#define CP_COMMIT() asm volatile("cp.async.commit_group;" ::: "memory")
template <int N>
__device__ __forceinline__ void cp_wait() {
    asm volatile("cp.async.wait_group %0;" :: "n"(N) : "memory");
}
__device__ __forceinline__ void ldsm4(uint32_t addr, uint32_t& r0, uint32_t& r1,
                                      uint32_t& r2, uint32_t& r3) {
    asm volatile("ldmatrix.sync.aligned.m8n8.x4.shared.b16 {%0,%1,%2,%3}, [%4];"
                 : "=r"(r0), "=r"(r1), "=r"(r2), "=r"(r3) : "r"(addr));
}
__device__ __forceinline__ void mma_f16(float* d,
                                        uint32_t a0, uint32_t a1,
                                        uint32_t a2, uint32_t a3,
                                        uint32_t b0, uint32_t b1) {
    asm volatile("mma.sync.aligned.m16n8k16.row.col.f32.f16.f16.f32 "
                 "{%0,%1,%2,%3}, {%4,%5,%6,%7}, {%8,%9}, {%0,%1,%2,%3};"
                 : "+f"(d[0]), "+f"(d[1]), "+f"(d[2]), "+f"(d[3])
                 : "r"(a0), "r"(a1), "r"(a2), "r"(a3), "r"(b0), "r"(b1));
}

// ---------------------------------------------------------------------------
// Kernel 0: W_out fp32 -> fp16
// ---------------------------------------------------------------------------
__global__ void to_half(const float* __restrict__ src,
                        __half* __restrict__ dst, int n)
{
    int i = blockIdx.x * blockDim.x + threadIdx.x;
    int stride = gridDim.x * blockDim.x;
    for (; i < n; i += stride) dst[i] = __float2half(src[i]);
}

// ---------------------------------------------------------------------------
// Kernel 0b: zero progress flags + ticket (re-run every graph replay)
// ---------------------------------------------------------------------------
__global__ void zero_flags()
{
    int t = threadIdx.x;
    if (t < 64) ((unsigned int*)g_progress)[t] = 0u;
    if (t == 64) g_ticket = 0u;
}

// ---------------------------------------------------------------------------
// Kernel 1: x_proj SGEMM (unchanged, ~123us)
// ---------------------------------------------------------------------------
template <bool GATHER>
__global__ __launch_bounds__(256, 2)
void gemm_nt(const float* __restrict__ A, const float* __restrict__ Bmat,
             const float* __restrict__ bias, float* __restrict__ C,
             const int* __restrict__ idx, int M, int N, int K)
{
    __shared__ float As[2][8][128];
    __shared__ float Bs[2][8][128];

    const int tid  = threadIdx.x;
    const int mblk = blockIdx.y * 128;
    const int nblk = blockIdx.x * 128;

    const int arow = tid >> 1;
    const int kq   = (tid & 1) * 4;

    const float* Aptr;
    if (GATHER) Aptr = A + (size_t)idx[mblk + arow] * K;
    else        Aptr = A + (size_t)(mblk + arow) * K;
    const float* Bptr = Bmat + (size_t)(nblk + arow) * K;

    const int ty = tid >> 4;
    const int tx = tid & 15;

    unsigned long long acc2[8][4];
    #pragma unroll
    for (int i = 0; i < 8; i++)
        #pragma unroll
        for (int p = 0; p < 4; p++) acc2[i][p] = 0ull;

    {
        float4 a4 = *(const float4*)(Aptr + kq);
        float4 b4 = *(const float4*)(Bptr + kq);
        #pragma unroll
        for (int i = 0; i < 4; i++) {
            As[0][kq + i][arow] = ((const float*)&a4)[i];
            Bs[0][kq + i][arow] = ((const float*)&b4)[i];
        }
    }
    __syncthreads();

    const int nkt = K >> 3;
    for (int kt = 0; kt < nkt; kt++) {
        const int cur = kt & 1, nxt = cur ^ 1;
        float4 a4n, b4n;
        const bool more = (kt + 1 < nkt);
        if (more) {
            a4n = *(const float4*)(Aptr + (kt + 1) * 8 + kq);
            b4n = *(const float4*)(Bptr + (kt + 1) * 8 + kq);
        }
        #pragma unroll
        for (int k = 0; k < 8; k++) {
            float af[8];
            *(float4*)&af[0] = *(const float4*)&As[cur][k][ty * 8];
            *(float4*)&af[4] = *(const float4*)&As[cur][k][ty * 8 + 4];
            unsigned long long bp[4];
            const unsigned long long* bq =
                (const unsigned long long*)&Bs[cur][k][tx * 8];
            #pragma unroll
            for (int p = 0; p < 4; p++) bp[p] = bq[p];
            #pragma unroll
            for (int i = 0; i < 8; i++) {
                unsigned long long ad = pack2(af[i], af[i]);
                #pragma unroll
                for (int p = 0; p < 4; p++) ffma2(acc2[i][p], ad, bp[p]);
            }
        }
        if (more) {
            #pragma unroll
            for (int i = 0; i < 4; i++) {
                As[nxt][kq + i][arow] = ((const float*)&a4n)[i];
                Bs[nxt][kq + i][arow] = ((const float*)&b4n)[i];
            }
        }
        __syncthreads();
    }

    float bv[8];
    #pragma unroll
    for (int j = 0; j < 8; j++) bv[j] = bias[nblk + tx * 8 + j];

    #pragma unroll
    for (int i = 0; i < 8; i++) {
        size_t row = (size_t)(mblk + ty * 8 + i);
        float* cp = C + row * (size_t)N + nblk + tx * 8;
        float v[8];
        #pragma unroll
        for (int p = 0; p < 4; p++) {
            float lo, hi;
            unpack2(acc2[i][p], lo, hi);
            v[2 * p]     = lo + bv[2 * p];
            v[2 * p + 1] = hi + bv[2 * p + 1];
        }
        *(float4*)cp       = make_float4(v[0], v[1], v[2], v[3]);
        *(float4*)(cp + 4) = make_float4(v[4], v[5], v[6], v[7]);
    }
}

// ---------------------------------------------------------------------------
// Fused kernel: 136 CTAs x 512 thr, cluster 8 (17 clusters — all wave-1).
// Blocks 0..63  : scan (cluster c = batch c), exact R6-measured body.
// Blocks 64..135: persistent GEMM workers (ticket + progress spin).
// Scan CTAs fall into the worker loop after finishing (drain on 136 SMs).
// GEMM tile: 256M x 128N, 16 warps (8M x 2N), K-chunk 64, 2-stage cp.async.
// smem/stage = (256+128) rows * 144B = 55296; 2 stages = 110592B.
// ---------------------------------------------------------------------------
#define OP_PITCH   144
#define W_STAGE    55296
#define W_BOFF     36864          // B region offset within stage (256*144)
#define FUSED_SMEM (2 * W_STAGE)  // 110592
#define NTILES     8000           // 8 chunks * 8 batches * 125 n-tiles

__global__ __launch_bounds__(512, 1) __cluster_dims__(8, 1, 1)
void fused_scan_logits(const float* __restrict__ xproj,
                       const float* __restrict__ hidden0,
                       const float* __restrict__ W_hh,
                       const float* __restrict__ b_hh,
                       __half* __restrict__ h16,
                       float* __restrict__ hfinal,
                       const __half* __restrict__ Bw,
                       const float* __restrict__ bias,
                       float* __restrict__ C)
{
    extern __shared__ char dsm[];
    __shared__ int sh_tile;
    const int tid = threadIdx.x;

    if (blockIdx.x < 64) {
        // =================== SCAN ROLE (R6-measured body) ===================
        float* h_buf = (float*)dsm;                  // [2][512]
        float* part  = (float*)(dsm + 4096);         // [8][64]

        const int batch = blockIdx.x >> 3;
        const int rank  = blockIdx.x & 7;
        const int out   = tid & 63;
        const int kc    = tid >> 6;
        const int kbase = kc * 64;
        const int grow  = rank * 64 + out;

        unsigned long long w2[32];
        {
            const unsigned long long* wq =
                (const unsigned long long*)(W_hh + (size_t)grow * H_ + kbase);
            #pragma unroll
            for (int j = 0; j < 32; j++) w2[j] = wq[j];
        }

        h_buf[tid] = hidden0[batch * H_ + tid];      // h_buf[0][tid]
        const float bhh = (tid < 64) ? b_hh[rank * 64 + tid] : 0.f;
        __syncthreads();
        asm volatile("barrier.cluster.arrive.aligned;" ::: "memory");
        asm volatile("barrier.cluster.wait.aligned;"   ::: "memory");

        const float* xp_b = xproj + (size_t)batch * S_ * H_ + rank * 64;
        __half*      hh_b = h16   + (size_t)batch * S_ * H_ + rank * 64;

        float hn = 0.f;
        for (int t = 0; t < S_; t++) {
            const int pb = t & 1;

            float xp = 0.f;
            if (tid < 64) xp = xp_b[(size_t)t * H_ + tid];

            const unsigned long long* hq =
                (const unsigned long long*)&h_buf[pb * H_ + kbase];
            unsigned long long a0 = 0ull, a1 = 0ull;
            #pragma unroll
            for (int j = 0; j < 16; j++) {
                ffma2(a0, w2[2 * j],     hq[2 * j]);
                ffma2(a1, w2[2 * j + 1], hq[2 * j + 1]);
            }
            float l0, hi0, l1, hi1;
            unpack2(a0, l0, hi0);
            unpack2(a1, l1, hi1);
            part[kc * 64 + out] = (l0 + hi0) + (l1 + hi1);
            __syncthreads();

            if (tid < 64) {
                float s = xp + bhh;
                #pragma unroll
                for (int c = 0; c < 8; c++) s += part[c * 64 + tid];
                hn = tanhf(s);
                hh_b[(size_t)t * H_ + tid] = __float2half(hn);   // <-- FIX

                uint32_t laddr = smem_u32(&h_buf[(pb ^ 1) * H_ + grow]);
                #pragma unroll
                for (int pr = 0; pr < 8; pr++) {
                    uint32_t paddr;
                    asm("mapa.shared::cluster.u32 %0, %1, %2;"
                        : "=r"(paddr) : "r"(laddr), "r"(pr));
                    asm volatile("st.shared::cluster.f32 [%0], %1;"
                                 :: "r"(paddr), "f"(hn) : "memory");
                }
            }
            __syncthreads();
            asm volatile("barrier.cluster.arrive.aligned;" ::: "memory");
            asm volatile("barrier.cluster.wait.aligned;"   ::: "memory");

            // publish completed 256-step chunk (this CTA's hseq slice is
            // globally visible via the release)
            if (((t & 255) == 255) && tid == 0) {
                asm volatile("red.release.gpu.global.add.u32 [%0], %1;"
                             :: "l"(&g_progress[batch][t >> 8]), "r"(1u)
                             : "memory");
            }
        }
        if (tid < 64) hfinal[batch * H_ + grow] = hn;
        __syncthreads();   // done with scan smem; fall into worker loop
    }

    // ====================== WORKER ROLE (all CTAs) ==========================
    const __half* Ah = h16;
    const uint32_t sbase = smem_u32(dsm);
    const int warp = tid >> 5, lane = tid & 31;
    const int wm = warp & 7;                 // 0..7 (M)
    const int wn = warp >> 3;                // 0..1 (N)

    const int arow = wm * 32 + (lane & 15);
    const int aoff = (lane >> 4) * 16;
    const int nrow = wn * 64 + (lane & 7) + ((lane >> 4) & 1) * 8;
    const int boff = ((lane >> 3) & 1) * 16;

    for (;;) {
        if (tid == 0) sh_tile = (int)atomicAdd(&g_ticket, 1u);
        __syncthreads();
        const int tile = sh_tile;
        if (tile >= NTILES) break;

        const int c   = tile / 1000;
        const int rem = tile - c * 1000;
        const int b   = rem / 125;
        const int nt  = rem - b * 125;
        const int mblk = b * S_ + c * 256;
        const int nblk = nt * 128;

        // wait until all 8 scan CTAs of batch b published chunk c
        if (tid == 0) {
            unsigned int v;
            for (;;) {
                asm volatile("ld.acquire.gpu.global.u32 %0, [%1];"
                             : "=r"(v) : "l"(&g_progress[b][c]) : "memory");
                if (v >= 8u) break;
                __nanosleep(256);
            }
        }
        __syncthreads();

        auto wload = [&](int kc, int st) {
            const uint32_t sst = sbase + (uint32_t)st * W_STAGE;
            #pragma unroll
            for (int j = 0; j < 6; j++) {
                int u = tid + 512 * j;
                if (u < 2048) {               // A: 256 rows x 8 chunks
                    int row = u >> 3, cc = u & 7;
                    cp_async16(sst + row * OP_PITCH + cc * 16,
                               (const char*)Ah +
                               (size_t)(mblk + row) * (H_ * 2) + kc * 128 + cc * 16);
                } else {                      // B: 128 rows x 8 chunks
                    int v2 = u - 2048;
                    int row = v2 >> 3, cc = v2 & 7;
                    cp_async16(sst + W_BOFF + row * OP_PITCH + cc * 16,
                               (const char*)Bw +
                               (size_t)(nblk + row) * (H_ * 2) + kc * 128 + cc * 16);
                }
            }
            CP_COMMIT();
        };

        float acc[2][8][4];
        #pragma unroll
        for (int mi = 0; mi < 2; mi++)
            #pragma unroll
            for (int ni = 0; ni < 8; ni++)
                #pragma unroll
                for (int q = 0; q < 4; q++) acc[mi][ni][q] = 0.f;

        wload(0, 0);
        wload(1, 1);

        #pragma unroll 1
        for (int kc = 0; kc < 8; kc++) {
            const int cur = kc & 1;
            if (kc < 7) cp_wait<1>(); else cp_wait<0>();
            __syncthreads();

            const uint32_t sst = sbase + (uint32_t)cur * W_STAGE;
            const uint32_t ahb = sst;
            const uint32_t bwb = sst + W_BOFF;

            #pragma unroll
            for (int ks = 0; ks < 4; ks++) {
                const int kb = ks * 32;
                uint32_t ah[2][4];
                #pragma unroll
                for (int mi = 0; mi < 2; mi++)
                    ldsm4(ahb + (arow + mi * 16) * OP_PITCH + kb + aoff,
                          ah[mi][0], ah[mi][1], ah[mi][2], ah[mi][3]);
                #pragma unroll
                for (int g = 0; g < 4; g++) {
                    uint32_t bh[4];
                    ldsm4(bwb + (nrow + g * 16) * OP_PITCH + kb + boff,
                          bh[0], bh[1], bh[2], bh[3]);
                    #pragma unroll
                    for (int mi = 0; mi < 2; mi++) {
                        mma_f16(acc[mi][2 * g],
                                ah[mi][0], ah[mi][1], ah[mi][2], ah[mi][3],
                                bh[0], bh[1]);
                        mma_f16(acc[mi][2 * g + 1],
                                ah[mi][0], ah[mi][1], ah[mi][2], ah[mi][3],
                                bh[2], bh[3]);
                    }
                }
            }
            __syncthreads();
            if (kc + 2 < 8) wload(kc + 2, cur);
        }

        // epilogue
        const int rg = mblk + wm * 32 + (lane >> 2);
        const int cg = nblk + wn * 64 + (lane & 3) * 2;
        #pragma unroll
        for (int mi = 0; mi < 2; mi++) {
            #pragma unroll
            for (int ni = 0; ni < 8; ni++) {
                const int row = rg + mi * 16;
                const int col = cg + ni * 8;
                const float b0 = __ldg(bias + col);
                const float b1 = __ldg(bias + col + 1);
                float2 v0 = make_float2(acc[mi][ni][0] + b0, acc[mi][ni][1] + b1);
                float2 v1 = make_float2(acc[mi][ni][2] + b0, acc[mi][ni][3] + b1);
                *(float2*)(C + (size_t)row * V_ + col)       = v0;
                *(float2*)(C + (size_t)(row + 8) * V_ + col) = v1;
            }
        }
        __syncthreads();   // tile done before smem reuse
    }
}

// ---------------------------------------------------------------------------
// Launch
// inputs: 0=x(i32)[B,S] 1=hidden[B,H] 2=embedding[V,E] 3=W_ih[H,E]
//         4=W_hh[H,H] 5=b_ih[H] 6=b_hh[H] 7=W_out[V,H] 8=b_out[V]
// output: logits [B,S,V] then h_final [B,H]
// ---------------------------------------------------------------------------
extern "C" void kernel_launch(void* const* d_in, const int* in_sizes, int n_in,
                              void* d_out, int out_size)
{
    const int*   x         = (const int*)  d_in[0];
    const float* hidden    = (const float*)d_in[1];
    const float* embedding = (const float*)d_in[2];
    const float* W_ih      = (const float*)d_in[3];
    const float* W_hh      = (const float*)d_in[4];
    const float* b_ih      = (const float*)d_in[5];
    const float* b_hh      = (const float*)d_in[6];
    const float* W_out     = (const float*)d_in[7];
    const float* b_out     = (const float*)d_in[8];
    float* out = (float*)d_out;

    float *xproj, *dummy;
    __half *h16, *w16;
    cudaGetSymbolAddress((void**)&xproj, g_xproj);
    cudaGetSymbolAddress((void**)&h16,   g_h16);
    cudaGetSymbolAddress((void**)&w16,   g_w16);
    cudaGetSymbolAddress((void**)&dummy, g_dummy_hf);

    float* hfin = ((long long)out_size >= VOUT + (long long)B_ * H_)
                      ? (out + VOUT) : dummy;

    static bool attr_done = false;
    if (!attr_done) {
        cudaFuncSetAttribute(fused_scan_logits,
                             cudaFuncAttributeMaxDynamicSharedMemorySize,
                             FUSED_SMEM);
        attr_done = true;
    }

    // 0) W_out -> fp16 ; zero overlap flags
    to_half<<<2048, 256>>>(W_out, w16, V_ * H_);
    zero_flags<<<1, 96>>>();

    // 1) x_proj = emb[x] @ W_ih^T + b_ih     [16384,512]
    gemm_nt<true><<<dim3(H_ / 128, MTOT / 128), 256>>>(
        embedding, W_ih, b_ih, xproj, x, MTOT, H_, E_);

    // 2+3) fused: scan (64 CTAs) + overlapped logits GEMM (72 workers + drain)
    fused_scan_logits<<<136, 512, FUSED_SMEM>>>(
        xproj, hidden, W_hh, b_hh, h16, hfin, w16, b_out, out);
}